// round 1
// baseline (speedup 1.0000x reference)
#include <cuda_runtime.h>
#include <math.h>

#define B_ 32768
#define M_ 10
#define BM_ (B_*M_)

// Scratch (allocation-free rule: __device__ globals)
__device__ float g_curx[(size_t)B_ * 1024];   // [z_top | r_top | h_top | q] per batch
__device__ float g_z  [(size_t)BM_ * 256];
__device__ float g_rp [(size_t)BM_ * 256];
__device__ float g_k  [(size_t)BM_ * 256];

__device__ __forceinline__ float sigmoidf_(float x) { return 1.f / (1.f + expf(-x)); }

// ---------------------------------------------------------------------------
// Generic 128x128-tile fp32 GEMM over K=256, 256 threads, 8x8 per thread.
// MODE 0: curx = cur @ {Wz,Wr,Wh,Wq}(top rows) + bias      -> g_curx
// MODE 1: {z,r} = sigmoid(prev @ {Wz,Wr}(bottom) + curx)   -> g_z, g_rp=r*prev
// MODE 2: cand  = tanh(g_rp @ Wh(bottom) + curx_h); u=(1-z)p+z*cand -> out(updated)
// MODE 3: k     = u @ Wk + bk                              -> g_k
// ---------------------------------------------------------------------------
template<int MODE>
__global__ __launch_bounds__(256)
void gemm_kernel(const float* __restrict__ A,
                 const float* __restrict__ Wa, const float* __restrict__ Wb,
                 const float* __restrict__ Wc, const float* __restrict__ Wd,
                 const float* __restrict__ ba, const float* __restrict__ bb,
                 const float* __restrict__ bc, const float* __restrict__ bd,
                 const float* __restrict__ prev,
                 float* __restrict__ out)
{
    __shared__ __align__(16) float As[16 * 132];   // padded: [k][m]
    __shared__ __align__(16) float Ws[16 * 128];   // [k][n]
    const int tid = threadIdx.x;
    const int tx = tid & 15, ty = tid >> 4;
    const int n0 = blockIdx.x * 128;
    const int m0 = blockIdx.y * 128;
    const int seg = n0 >> 8;        // 256-col weight segment
    const int ncol = n0 & 255;      // col offset within segment
    const float* W    = (seg == 0) ? Wa : (seg == 1) ? Wb : (seg == 2) ? Wc : Wd;
    const float* bias = (seg == 0) ? ba : (seg == 1) ? bb : (seg == 2) ? bc : bd;
    const float* Ap   = (MODE == 2) ? g_rp : A;

    float acc[8][8];
    #pragma unroll
    for (int i = 0; i < 8; i++)
        #pragma unroll
        for (int j = 0; j < 8; j++) acc[i][j] = 0.f;

    for (int k0 = 0; k0 < 256; k0 += 16) {
        #pragma unroll
        for (int u = 0; u < 8; u++) {
            int idx = u * 256 + tid;
            int m = idx >> 4, k = idx & 15;
            As[k * 132 + m] = Ap[(size_t)(m0 + m) * 256 + k0 + k];
        }
        #pragma unroll
        for (int u = 0; u < 8; u++) {
            int idx = u * 256 + tid;
            int k = idx >> 7, n = idx & 127;
            Ws[k * 128 + n] = W[(size_t)(k0 + k) * 256 + ncol + n];
        }
        __syncthreads();
        #pragma unroll
        for (int kk = 0; kk < 16; kk++) {
            float a[8], w[8];
            *(float4*)(a)     = *(const float4*)(As + kk * 132 + ty * 8);
            *(float4*)(a + 4) = *(const float4*)(As + kk * 132 + ty * 8 + 4);
            *(float4*)(w)     = *(const float4*)(Ws + kk * 128 + tx * 8);
            *(float4*)(w + 4) = *(const float4*)(Ws + kk * 128 + tx * 8 + 4);
            #pragma unroll
            for (int i = 0; i < 8; i++)
                #pragma unroll
                for (int j = 0; j < 8; j++) acc[i][j] = fmaf(a[i], w[j], acc[i][j]);
        }
        __syncthreads();
    }

    #pragma unroll
    for (int i = 0; i < 8; i++) {
        const int row = m0 + ty * 8 + i;
        const int b = (MODE == 0) ? row : (row / 10);
        #pragma unroll
        for (int j = 0; j < 8; j++) {
            const int h = ncol + tx * 8 + j;   // col within 256-wide segment
            float v = acc[i][j];
            if (MODE == 0) {
                g_curx[(size_t)row * 1024 + seg * 256 + h] = v + bias[h];
            } else if (MODE == 1) {
                if (seg == 0) {
                    float z = sigmoidf_(v + g_curx[(size_t)b * 1024 + h]);
                    g_z[(size_t)row * 256 + h] = z;
                } else {
                    float r = sigmoidf_(v + g_curx[(size_t)b * 1024 + 256 + h]);
                    g_rp[(size_t)row * 256 + h] = r * prev[(size_t)row * 256 + h];
                }
            } else if (MODE == 2) {
                float cand = tanhf(v + g_curx[(size_t)b * 1024 + 512 + h]);
                float z = g_z[(size_t)row * 256 + h];
                float p = prev[(size_t)row * 256 + h];
                out[(size_t)row * 256 + h] = (1.f - z) * p + z * cand;
            } else {  // MODE 3
                g_k[(size_t)row * 256 + h] = v + bias[h];
            }
        }
    }
}

// ---------------------------------------------------------------------------
// Attention + fuse + LayerNorm. One CTA handles GB=16 batch rows.
// ---------------------------------------------------------------------------
__global__ __launch_bounds__(256)
void attn_fuse_kernel(const float* __restrict__ cur,
                      float* __restrict__ d_out,
                      const float* __restrict__ Wo, const float* __restrict__ bo,
                      const float* __restrict__ gamma, const float* __restrict__ beta)
{
    const int GB = 16;
    __shared__ __align__(16) float sbuf[GB * 512];  // phase A/B: q; phase D/E: x=[cur|weighted]; then pre-LN
    __shared__ float ss[GB * 8 * 10];               // scores / softmax
    __shared__ float sattn[GB * 10];
    const int tid = threadIdx.x;
    const int b0 = blockIdx.x * GB;
    float* upd      = d_out + (size_t)B_ * 256;
    float* attn_out = d_out + (size_t)B_ * 256 + (size_t)BM_ * 256;

    // A: load q
    for (int idx = tid; idx < GB * 256; idx += 256) {
        int bi = idx >> 8, h = idx & 255;
        sbuf[bi * 512 + h] = g_curx[(size_t)(b0 + bi) * 1024 + 768 + h];
    }
    __syncthreads();

    // B: scores[bi][n][m] = (q_n . k_{m,n}) / sqrt(32)
    const float scale = 0.17677669529663687f;
    for (int t = tid; t < GB * 80; t += 256) {
        int bi = t / 80, rem = t % 80, n = rem / 10, m = rem % 10;
        const float* kp = g_k + ((size_t)((b0 + bi) * 10 + m)) * 256 + n * 32;
        const float* qp = sbuf + bi * 512 + n * 32;
        float s = 0.f;
        #pragma unroll
        for (int d4 = 0; d4 < 32; d4 += 4) {
            float4 kv = *(const float4*)(kp + d4);
            float4 qv = *(const float4*)(qp + d4);
            s += kv.x * qv.x + kv.y * qv.y + kv.z * qv.z + kv.w * qv.w;
        }
        ss[t] = s * scale;
    }
    __syncthreads();

    // C: softmax over m per (bi, n)
    for (int t = tid; t < GB * 8; t += 256) {
        float* row = ss + t * 10;
        float mx = row[0];
        #pragma unroll
        for (int m = 1; m < 10; m++) mx = fmaxf(mx, row[m]);
        float e[10], sum = 0.f;
        #pragma unroll
        for (int m = 0; m < 10; m++) { e[m] = expf(row[m] - mx); sum += e[m]; }
        float inv = 1.f / sum;
        #pragma unroll
        for (int m = 0; m < 10; m++) row[m] = e[m] * inv;
    }
    __syncthreads();

    // head mean -> attn weights
    for (int t = tid; t < GB * 10; t += 256) {
        int bi = t / 10, m = t % 10;
        float s = 0.f;
        #pragma unroll
        for (int n = 0; n < 8; n++) s += ss[(bi * 8 + n) * 10 + m];
        s *= 0.125f;
        sattn[t] = s;
        attn_out[(size_t)(b0 + bi) * 10 + m] = s;
    }
    __syncthreads();

    // D: weighted memory; build x = [cur | weighted]
    for (int idx = tid; idx < GB * 256; idx += 256) {
        int bi = idx >> 8, h = idx & 255;
        size_t base = ((size_t)(b0 + bi) * 10) * 256 + h;
        float s = 0.f;
        #pragma unroll
        for (int m = 0; m < 10; m++) s += upd[base + m * 256] * sattn[bi * 10 + m];
        sbuf[bi * 512 + h]       = cur[(size_t)(b0 + bi) * 256 + h];
        sbuf[bi * 512 + 256 + h] = s;
    }
    __syncthreads();

    // E: fused_pre = x @ Wo + bo ; thread owns output column d = tid
    float accv[GB];
    #pragma unroll
    for (int bi = 0; bi < GB; bi++) accv[bi] = bo[tid];
    for (int c = 0; c < 512; c += 4) {
        float w0 = Wo[(size_t)(c + 0) * 256 + tid];
        float w1 = Wo[(size_t)(c + 1) * 256 + tid];
        float w2 = Wo[(size_t)(c + 2) * 256 + tid];
        float w3 = Wo[(size_t)(c + 3) * 256 + tid];
        #pragma unroll
        for (int bi = 0; bi < GB; bi++) {
            float4 xv = *(const float4*)(sbuf + bi * 512 + c);
            accv[bi] += xv.x * w0 + xv.y * w1 + xv.z * w2 + xv.w * w3;
        }
    }
    __syncthreads();
    #pragma unroll
    for (int bi = 0; bi < GB; bi++) sbuf[bi * 256 + tid] = accv[bi];
    __syncthreads();

    // F: LayerNorm, one warp per 2 rows
    int wid = tid >> 5, lane = tid & 31;
    for (int bi = wid; bi < GB; bi += 8) {
        float v[8], sum = 0.f;
        #pragma unroll
        for (int i = 0; i < 8; i++) { v[i] = sbuf[bi * 256 + lane + 32 * i]; sum += v[i]; }
        #pragma unroll
        for (int o = 16; o > 0; o >>= 1) sum += __shfl_xor_sync(0xffffffffu, sum, o);
        float mu = sum * (1.f / 256.f);
        float sq = 0.f;
        #pragma unroll
        for (int i = 0; i < 8; i++) { float d = v[i] - mu; sq += d * d; }
        #pragma unroll
        for (int o = 16; o > 0; o >>= 1) sq += __shfl_xor_sync(0xffffffffu, sq, o);
        float rstd = rsqrtf(sq * (1.f / 256.f) + 1e-5f);
        size_t ob = (size_t)(b0 + bi) * 256;
        #pragma unroll
        for (int i = 0; i < 8; i++) {
            int d_ = lane + 32 * i;
            d_out[ob + d_] = (v[i] - mu) * rstd * gamma[d_] + beta[d_];
        }
    }
}

extern "C" void kernel_launch(void* const* d_in, const int* in_sizes, int n_in,
                              void* d_out, int out_size)
{
    (void)in_sizes; (void)n_in; (void)out_size;
    const float* cur    = (const float*)d_in[0];
    const float* prev   = (const float*)d_in[1];
    const float* Wz     = (const float*)d_in[2];
    const float* bz     = (const float*)d_in[3];
    const float* Wr     = (const float*)d_in[4];
    const float* br     = (const float*)d_in[5];
    const float* Wh     = (const float*)d_in[6];
    const float* bh     = (const float*)d_in[7];
    const float* Wq     = (const float*)d_in[8];
    const float* bq     = (const float*)d_in[9];
    const float* Wk     = (const float*)d_in[10];
    const float* bk     = (const float*)d_in[11];
    const float* Wo     = (const float*)d_in[12];
    const float* bo     = (const float*)d_in[13];
    const float* gamma2 = (const float*)d_in[14];
    const float* beta2  = (const float*)d_in[15];
    float* out = (float*)d_out;
    float* upd = out + (size_t)B_ * 256;   // updated_memory region of d_out

    dim3 blk(256);
    // 1) cur projections: [B,256] @ [256,1024] (Wz/Wr/Wh top rows + Wq), + biases
    gemm_kernel<0><<<dim3(8, B_ / 128), blk>>>(cur, Wz, Wr, Wh, Wq,
                                               bz, br, bh, bq, nullptr, nullptr);
    // 2) z/r: [BM,256] @ [256,512] (Wz/Wr bottom rows), sigmoid epilogue
    gemm_kernel<1><<<dim3(4, BM_ / 128), blk>>>(prev, Wz + 65536, Wr + 65536, nullptr, nullptr,
                                                nullptr, nullptr, nullptr, nullptr, prev, nullptr);
    // 3) cand + GRU update -> updated_memory (d_out)
    gemm_kernel<2><<<dim3(2, BM_ / 128), blk>>>(nullptr, Wh + 65536, nullptr, nullptr, nullptr,
                                                nullptr, nullptr, nullptr, nullptr, prev, upd);
    // 4) k projection
    gemm_kernel<3><<<dim3(2, BM_ / 128), blk>>>(upd, Wk, nullptr, nullptr, nullptr,
                                                bk, nullptr, nullptr, nullptr, nullptr, nullptr);
    // 5) attention + weighted memory + output proj + layernorm
    attn_fuse_kernel<<<dim3(B_ / 16), blk>>>(cur, out, Wo, bo, gamma2, beta2);
}

// round 2
// speedup vs baseline: 1.8400x; 1.8400x over previous
#include <cuda_runtime.h>
#include <math.h>
#include <stdint.h>

#define B_ 32768
#define M_ 10
#define BM_ (B_*M_)

// Scratch (allocation-free rule: __device__ globals)
__device__ float g_curx[(size_t)B_ * 1024];   // [z_top | r_top | h_top | q] per batch
__device__ float g_z  [(size_t)BM_ * 256];
__device__ float g_rp [(size_t)BM_ * 256];
__device__ float g_k  [(size_t)BM_ * 256];

__device__ __forceinline__ float sigmoidf_(float x) { return 1.f / (1.f + expf(-x)); }

__device__ __forceinline__ uint32_t f2tf32(float x) {
    uint32_t r;
    asm("cvt.rna.tf32.f32 %0, %1;" : "=r"(r) : "f"(x));
    return r;
}

__device__ __forceinline__ void mma_tf32(float c[4], const uint32_t a[4], const uint32_t b[2]) {
    asm volatile(
        "mma.sync.aligned.m16n8k8.row.col.f32.tf32.tf32.f32 "
        "{%0,%1,%2,%3}, {%4,%5,%6,%7}, {%8,%9}, {%0,%1,%2,%3};"
        : "+f"(c[0]), "+f"(c[1]), "+f"(c[2]), "+f"(c[3])
        : "r"(a[0]), "r"(a[1]), "r"(a[2]), "r"(a[3]), "r"(b[0]), "r"(b[1]));
}

// ---------------------------------------------------------------------------
// tf32 tensor-core GEMM, 128x128 tile over K=256. 256 threads, 8 warps (2m x 4n),
// warp tile 64x32 (4 m16 x 4 n8 mma tiles). Register-prefetch pipeline.
// MODE 0: curx = cur @ {Wz,Wr,Wh,Wq}(top rows) + bias      -> g_curx
// MODE 1: {z,r} = sigmoid(prev @ {Wz,Wr}(bottom) + curx)   -> g_z, g_rp=r*prev
// MODE 2: cand  = tanh(g_rp @ Wh(bottom) + curx_h); u=(1-z)p+z*cand -> out(updated)
// MODE 3: k     = u @ Wk + bk                              -> g_k
// ---------------------------------------------------------------------------
#define AS_STRIDE 36
#define BS_STRIDE 136

template<int MODE>
__global__ __launch_bounds__(256)
void mma_gemm(const float* __restrict__ A,
              const float* __restrict__ Wa, const float* __restrict__ Wb,
              const float* __restrict__ Wc, const float* __restrict__ Wd,
              const float* __restrict__ ba, const float* __restrict__ bb,
              const float* __restrict__ bc, const float* __restrict__ bd,
              const float* __restrict__ prev,
              float* __restrict__ out)
{
    __shared__ __align__(16) float As[128 * AS_STRIDE];   // [m][k], k-chunk of 32
    __shared__ __align__(16) float Bs[32 * BS_STRIDE];    // [k][n]

    const int tid  = threadIdx.x;
    const int lane = tid & 31;
    const int warp = tid >> 5;
    const int wm   = warp >> 2;          // 0..1  (m)
    const int wn   = warp & 3;           // 0..3  (n)
    const int q    = lane >> 2;          // groupID 0..7
    const int t4   = lane & 3;           // thread-in-group 0..3

    const int n0  = blockIdx.x * 128;
    const int m0  = blockIdx.y * 128;
    const int seg = n0 >> 8;             // 256-col weight segment
    const int ncol = n0 & 255;

    const float* W    = (seg == 0) ? Wa : (seg == 1) ? Wb : (seg == 2) ? Wc : Wd;
    const float* bias = (seg == 0) ? ba : (seg == 1) ? bb : (seg == 2) ? bc : bd;
    const float* Ap   = (MODE == 2) ? g_rp : A;

    float acc[4][4][4];
    #pragma unroll
    for (int i = 0; i < 4; i++)
        #pragma unroll
        for (int j = 0; j < 4; j++)
            #pragma unroll
            for (int v = 0; v < 4; v++) acc[i][j][v] = 0.f;

    float4 ar[4], br[4];

    // prologue LDG (chunk 0)
    {
        const int k0 = 0;
        #pragma unroll
        for (int i = 0; i < 4; i++) {
            int idx = i * 256 + tid;
            ar[i] = *(const float4*)(Ap + (size_t)(m0 + (idx >> 3)) * 256 + k0 + ((idx & 7) << 2));
            br[i] = *(const float4*)(W  + (size_t)(k0 + (idx >> 5)) * 256 + ncol + ((idx & 31) << 2));
        }
    }

    for (int c = 0; c < 8; c++) {
        // STS staged chunk
        #pragma unroll
        for (int i = 0; i < 4; i++) {
            int idx = i * 256 + tid;
            *(float4*)(As + (idx >> 3) * AS_STRIDE + ((idx & 7) << 2)) = ar[i];
            *(float4*)(Bs + (idx >> 5) * BS_STRIDE + ((idx & 31) << 2)) = br[i];
        }
        __syncthreads();

        // prefetch next chunk while computing this one
        if (c < 7) {
            const int k0 = (c + 1) * 32;
            #pragma unroll
            for (int i = 0; i < 4; i++) {
                int idx = i * 256 + tid;
                ar[i] = *(const float4*)(Ap + (size_t)(m0 + (idx >> 3)) * 256 + k0 + ((idx & 7) << 2));
                br[i] = *(const float4*)(W  + (size_t)(k0 + (idx >> 5)) * 256 + ncol + ((idx & 31) << 2));
            }
        }

        // compute 4 k8-steps
        #pragma unroll
        for (int kk = 0; kk < 4; kk++) {
            uint32_t a[4][4], b[4][2];
            const int col = kk * 8 + t4;
            #pragma unroll
            for (int mt = 0; mt < 4; mt++) {
                const int r0 = wm * 64 + mt * 16 + q;
                a[mt][0] = f2tf32(As[r0 * AS_STRIDE + col]);
                a[mt][1] = f2tf32(As[(r0 + 8) * AS_STRIDE + col]);
                a[mt][2] = f2tf32(As[r0 * AS_STRIDE + col + 4]);
                a[mt][3] = f2tf32(As[(r0 + 8) * AS_STRIDE + col + 4]);
            }
            #pragma unroll
            for (int nt = 0; nt < 4; nt++) {
                const int nb = wn * 32 + nt * 8 + q;
                b[nt][0] = f2tf32(Bs[(kk * 8 + t4) * BS_STRIDE + nb]);
                b[nt][1] = f2tf32(Bs[(kk * 8 + t4 + 4) * BS_STRIDE + nb]);
            }
            #pragma unroll
            for (int mt = 0; mt < 4; mt++)
                #pragma unroll
                for (int nt = 0; nt < 4; nt++)
                    mma_tf32(acc[mt][nt], a[mt], b[nt]);
        }
        __syncthreads();
    }

    // ---------------- epilogue ----------------
    #pragma unroll
    for (int mt = 0; mt < 4; mt++) {
        #pragma unroll
        for (int nt = 0; nt < 4; nt++) {
            const int hl = wn * 32 + nt * 8 + 2 * t4;  // col within 128 tile
            const int h  = ncol + hl;                  // col within 256 segment
            #pragma unroll
            for (int half = 0; half < 2; half++) {
                const int row = m0 + wm * 64 + mt * 16 + q + half * 8;
                const float v0 = acc[mt][nt][half * 2 + 0];
                const float v1 = acc[mt][nt][half * 2 + 1];
                if (MODE == 0) {
                    float2 bb2 = *(const float2*)(bias + h);
                    float2 o = make_float2(v0 + bb2.x, v1 + bb2.y);
                    *(float2*)(g_curx + (size_t)row * 1024 + seg * 256 + h) = o;
                } else if (MODE == 1) {
                    const int b = row / 10;
                    if (seg == 0) {
                        float2 cx = *(const float2*)(g_curx + (size_t)b * 1024 + h);
                        float2 o = make_float2(sigmoidf_(v0 + cx.x), sigmoidf_(v1 + cx.y));
                        *(float2*)(g_z + (size_t)row * 256 + h) = o;
                    } else {
                        float2 cx = *(const float2*)(g_curx + (size_t)b * 1024 + 256 + h);
                        float2 pv = *(const float2*)(prev + (size_t)row * 256 + h);
                        float2 o = make_float2(sigmoidf_(v0 + cx.x) * pv.x,
                                               sigmoidf_(v1 + cx.y) * pv.y);
                        *(float2*)(g_rp + (size_t)row * 256 + h) = o;
                    }
                } else if (MODE == 2) {
                    const int b = row / 10;
                    float2 cx = *(const float2*)(g_curx + (size_t)b * 1024 + 512 + h);
                    float2 zz = *(const float2*)(g_z + (size_t)row * 256 + h);
                    float2 pv = *(const float2*)(prev + (size_t)row * 256 + h);
                    float c0 = tanhf(v0 + cx.x), c1 = tanhf(v1 + cx.y);
                    float2 o = make_float2((1.f - zz.x) * pv.x + zz.x * c0,
                                           (1.f - zz.y) * pv.y + zz.y * c1);
                    *(float2*)(out + (size_t)row * 256 + h) = o;
                } else {  // MODE 3
                    float2 bb2 = *(const float2*)(bias + h);
                    float2 o = make_float2(v0 + bb2.x, v1 + bb2.y);
                    *(float2*)(g_k + (size_t)row * 256 + h) = o;
                }
            }
        }
    }
}

// ---------------------------------------------------------------------------
// Attention + fuse + LayerNorm. One CTA handles GB=16 batch rows. (fp32, mem-bound)
// ---------------------------------------------------------------------------
__global__ __launch_bounds__(256)
void attn_fuse_kernel(const float* __restrict__ cur,
                      float* __restrict__ d_out,
                      const float* __restrict__ Wo, const float* __restrict__ bo,
                      const float* __restrict__ gamma, const float* __restrict__ beta)
{
    const int GB = 16;
    __shared__ __align__(16) float sbuf[GB * 512];
    __shared__ float ss[GB * 8 * 10];
    __shared__ float sattn[GB * 10];
    const int tid = threadIdx.x;
    const int b0 = blockIdx.x * GB;
    float* upd      = d_out + (size_t)B_ * 256;
    float* attn_out = d_out + (size_t)B_ * 256 + (size_t)BM_ * 256;

    // A: load q
    for (int idx = tid; idx < GB * 256; idx += 256) {
        int bi = idx >> 8, h = idx & 255;
        sbuf[bi * 512 + h] = g_curx[(size_t)(b0 + bi) * 1024 + 768 + h];
    }
    __syncthreads();

    // B: scores
    const float scale = 0.17677669529663687f;
    for (int t = tid; t < GB * 80; t += 256) {
        int bi = t / 80, rem = t % 80, n = rem / 10, m = rem % 10;
        const float* kp = g_k + ((size_t)((b0 + bi) * 10 + m)) * 256 + n * 32;
        const float* qp = sbuf + bi * 512 + n * 32;
        float s = 0.f;
        #pragma unroll
        for (int d4 = 0; d4 < 32; d4 += 4) {
            float4 kv = *(const float4*)(kp + d4);
            float4 qv = *(const float4*)(qp + d4);
            s += kv.x * qv.x + kv.y * qv.y + kv.z * qv.z + kv.w * qv.w;
        }
        ss[t] = s * scale;
    }
    __syncthreads();

    // C: softmax over m
    for (int t = tid; t < GB * 8; t += 256) {
        float* row = ss + t * 10;
        float mx = row[0];
        #pragma unroll
        for (int m = 1; m < 10; m++) mx = fmaxf(mx, row[m]);
        float e[10], sum = 0.f;
        #pragma unroll
        for (int m = 0; m < 10; m++) { e[m] = expf(row[m] - mx); sum += e[m]; }
        float inv = 1.f / sum;
        #pragma unroll
        for (int m = 0; m < 10; m++) row[m] = e[m] * inv;
    }
    __syncthreads();

    // head mean
    for (int t = tid; t < GB * 10; t += 256) {
        int bi = t / 10, m = t % 10;
        float s = 0.f;
        #pragma unroll
        for (int n = 0; n < 8; n++) s += ss[(bi * 8 + n) * 10 + m];
        s *= 0.125f;
        sattn[t] = s;
        attn_out[(size_t)(b0 + bi) * 10 + m] = s;
    }
    __syncthreads();

    // D: weighted memory; x = [cur | weighted]
    for (int idx = tid; idx < GB * 256; idx += 256) {
        int bi = idx >> 8, h = idx & 255;
        size_t base = ((size_t)(b0 + bi) * 10) * 256 + h;
        float s = 0.f;
        #pragma unroll
        for (int m = 0; m < 10; m++) s += upd[base + m * 256] * sattn[bi * 10 + m];
        sbuf[bi * 512 + h]       = cur[(size_t)(b0 + bi) * 256 + h];
        sbuf[bi * 512 + 256 + h] = s;
    }
    __syncthreads();

    // E: fused_pre = x @ Wo + bo
    float accv[GB];
    #pragma unroll
    for (int bi = 0; bi < GB; bi++) accv[bi] = bo[tid];
    for (int c = 0; c < 512; c += 4) {
        float w0 = Wo[(size_t)(c + 0) * 256 + tid];
        float w1 = Wo[(size_t)(c + 1) * 256 + tid];
        float w2 = Wo[(size_t)(c + 2) * 256 + tid];
        float w3 = Wo[(size_t)(c + 3) * 256 + tid];
        #pragma unroll
        for (int bi = 0; bi < GB; bi++) {
            float4 xv = *(const float4*)(sbuf + bi * 512 + c);
            accv[bi] += xv.x * w0 + xv.y * w1 + xv.z * w2 + xv.w * w3;
        }
    }
    __syncthreads();
    #pragma unroll
    for (int bi = 0; bi < GB; bi++) sbuf[bi * 256 + tid] = accv[bi];
    __syncthreads();

    // F: LayerNorm
    int wid = tid >> 5, lane = tid & 31;
    for (int bi = wid; bi < GB; bi += 8) {
        float v[8], sum = 0.f;
        #pragma unroll
        for (int i = 0; i < 8; i++) { v[i] = sbuf[bi * 256 + lane + 32 * i]; sum += v[i]; }
        #pragma unroll
        for (int o = 16; o > 0; o >>= 1) sum += __shfl_xor_sync(0xffffffffu, sum, o);
        float mu = sum * (1.f / 256.f);
        float sq = 0.f;
        #pragma unroll
        for (int i = 0; i < 8; i++) { float d = v[i] - mu; sq += d * d; }
        #pragma unroll
        for (int o = 16; o > 0; o >>= 1) sq += __shfl_xor_sync(0xffffffffu, sq, o);
        float rstd = rsqrtf(sq * (1.f / 256.f) + 1e-5f);
        size_t ob = (size_t)(b0 + bi) * 256;
        #pragma unroll
        for (int i = 0; i < 8; i++) {
            int d_ = lane + 32 * i;
            d_out[ob + d_] = (v[i] - mu) * rstd * gamma[d_] + beta[d_];
        }
    }
}

extern "C" void kernel_launch(void* const* d_in, const int* in_sizes, int n_in,
                              void* d_out, int out_size)
{
    (void)in_sizes; (void)n_in; (void)out_size;
    const float* cur    = (const float*)d_in[0];
    const float* prev   = (const float*)d_in[1];
    const float* Wz     = (const float*)d_in[2];
    const float* bz     = (const float*)d_in[3];
    const float* Wr     = (const float*)d_in[4];
    const float* br     = (const float*)d_in[5];
    const float* Wh     = (const float*)d_in[6];
    const float* bh     = (const float*)d_in[7];
    const float* Wq     = (const float*)d_in[8];
    const float* bq     = (const float*)d_in[9];
    const float* Wk     = (const float*)d_in[10];
    const float* bk     = (const float*)d_in[11];
    const float* Wo     = (const float*)d_in[12];
    const float* bo     = (const float*)d_in[13];
    const float* gamma2 = (const float*)d_in[14];
    const float* beta2  = (const float*)d_in[15];
    float* out = (float*)d_out;
    float* upd = out + (size_t)B_ * 256;

    dim3 blk(256);
    // 1) cur projections: [B,256] @ [256,1024]
    mma_gemm<0><<<dim3(8, B_ / 128), blk>>>(cur, Wz, Wr, Wh, Wq,
                                            bz, br, bh, bq, nullptr, nullptr);
    // 2) z/r gates: [BM,256] @ [256,512]
    mma_gemm<1><<<dim3(4, BM_ / 128), blk>>>(prev, Wz + 65536, Wr + 65536, nullptr, nullptr,
                                             nullptr, nullptr, nullptr, nullptr, prev, nullptr);
    // 3) cand + GRU update -> updated_memory
    mma_gemm<2><<<dim3(2, BM_ / 128), blk>>>(nullptr, Wh + 65536, nullptr, nullptr, nullptr,
                                             nullptr, nullptr, nullptr, nullptr, prev, upd);
    // 4) k projection
    mma_gemm<3><<<dim3(2, BM_ / 128), blk>>>(upd, Wk, nullptr, nullptr, nullptr,
                                             bk, nullptr, nullptr, nullptr, nullptr, nullptr);
    // 5) attention + weighted memory + output proj + layernorm
    attn_fuse_kernel<<<dim3(B_ / 16), blk>>>(cur, out, Wo, bo, gamma2, beta2);
}

// round 3
// speedup vs baseline: 2.7131x; 1.4745x over previous
#include <cuda_runtime.h>
#include <math.h>
#include <stdint.h>

#define B_ 32768
#define M_ 10
#define BM_ (B_*M_)

// Scratch (allocation-free rule: __device__ globals)
__device__ float g_curx[(size_t)B_ * 1024];   // [z_top | r_top | h_top | q] per batch
__device__ float g_z  [(size_t)BM_ * 256];
__device__ float g_rp [(size_t)BM_ * 256];
__device__ float g_k  [(size_t)BM_ * 256];

__device__ __forceinline__ float sigmoidf_(float x) { return 1.f / (1.f + expf(-x)); }

__device__ __forceinline__ uint32_t smem_u32(const void* p) {
    return (uint32_t)__cvta_generic_to_shared(p);
}
__device__ __forceinline__ void cp_async16(uint32_t s, const void* g) {
    asm volatile("cp.async.cg.shared.global [%0], [%1], 16;\n" :: "r"(s), "l"(g));
}
__device__ __forceinline__ void cp_commit() {
    asm volatile("cp.async.commit_group;\n");
}
template<int N>
__device__ __forceinline__ void cp_wait() {
    asm volatile("cp.async.wait_group %0;\n" :: "n"(N));
}

__device__ __forceinline__ void mma_tf32(float c[4], const uint32_t a[4], const uint32_t b[2]) {
    asm volatile(
        "mma.sync.aligned.m16n8k8.row.col.f32.tf32.tf32.f32 "
        "{%0,%1,%2,%3}, {%4,%5,%6,%7}, {%8,%9}, {%0,%1,%2,%3};"
        : "+f"(c[0]), "+f"(c[1]), "+f"(c[2]), "+f"(c[3])
        : "r"(a[0]), "r"(a[1]), "r"(a[2]), "r"(a[3]), "r"(b[0]), "r"(b[1]));
}

// ---------------------------------------------------------------------------
// tf32 tensor-core GEMM, 128x128 tile over K=256, cp.async double-buffered.
// 256 threads, 8 warps (2m x 4n), warp tile 64x32.
// MODE 0: curx = cur @ {Wz,Wr,Wh,Wq}(top rows) + bias      -> g_curx
// MODE 1: {z,r} = sigmoid(prev @ {Wz,Wr}(bottom) + curx)   -> g_z, g_rp=r*prev
// MODE 2: cand  = tanh(g_rp @ Wh(bottom) + curx_h); u=(1-z)p+z*cand -> out(updated)
// MODE 3: k     = u @ Wk + bk                              -> g_k
// ---------------------------------------------------------------------------
#define AS_STRIDE 36
#define BS_STRIDE 136
#define AS_ELEMS (128 * AS_STRIDE)
#define BS_ELEMS (32 * BS_STRIDE)

template<int MODE>
__global__ __launch_bounds__(256, 2)
void mma_gemm(const float* __restrict__ A,
              const float* __restrict__ Wa, const float* __restrict__ Wb,
              const float* __restrict__ Wc, const float* __restrict__ Wd,
              const float* __restrict__ ba, const float* __restrict__ bb,
              const float* __restrict__ bc, const float* __restrict__ bd,
              const float* __restrict__ prev,
              float* __restrict__ out)
{
    __shared__ __align__(16) float As[2][AS_ELEMS];   // [m][k] chunk of 32, pad 36
    __shared__ __align__(16) float Bs[2][BS_ELEMS];   // [k][n] chunk, pad 136

    const int tid  = threadIdx.x;
    const int lane = tid & 31;
    const int warp = tid >> 5;
    const int wm   = warp >> 2;          // 0..1  (m)
    const int wn   = warp & 3;           // 0..3  (n)
    const int q    = lane >> 2;          // 0..7
    const int t4   = lane & 3;           // 0..3

    const int n0  = blockIdx.x * 128;
    const int m0  = blockIdx.y * 128;
    const int seg = n0 >> 8;
    const int ncol = n0 & 255;

    const float* W    = (seg == 0) ? Wa : (seg == 1) ? Wb : (seg == 2) ? Wc : Wd;
    const float* bias = (seg == 0) ? ba : (seg == 1) ? bb : (seg == 2) ? bc : bd;
    const float* Ap   = (MODE == 2) ? g_rp : A;

    // Per-thread fixed copy coordinates (4 A granules, 4 B granules of 16B)
    const int am  = tid >> 1;                 // A: granule g = i*256+tid -> m = g>>3
    const int ac4 = (tid & 1) << 2;           //    but do it explicitly below
    (void)am; (void)ac4;

    float acc[4][4][4];
    #pragma unroll
    for (int i = 0; i < 4; i++)
        #pragma unroll
        for (int j = 0; j < 4; j++)
            #pragma unroll
            for (int v = 0; v < 4; v++) acc[i][j][v] = 0.f;

    // copy one k-chunk into buffer bi
    auto load_chunk = [&](int bi, int k0) {
        #pragma unroll
        for (int i = 0; i < 4; i++) {
            int g = i * 256 + tid;            // A granules: 1024 total
            int m = g >> 3, c4 = (g & 7) << 2;
            cp_async16(smem_u32(&As[bi][m * AS_STRIDE + c4]),
                       Ap + (size_t)(m0 + m) * 256 + k0 + c4);
        }
        #pragma unroll
        for (int i = 0; i < 4; i++) {
            int g = i * 256 + tid;            // B granules: 1024 total
            int k = g >> 5, n4 = (g & 31) << 2;
            cp_async16(smem_u32(&Bs[bi][k * BS_STRIDE + n4]),
                       W + (size_t)(k0 + k) * 256 + ncol + n4);
        }
        cp_commit();
    };

    load_chunk(0, 0);

    for (int c = 0; c < 8; c++) {
        const int buf = c & 1;
        if (c < 7) load_chunk(buf ^ 1, (c + 1) * 32);
        if (c < 7) cp_wait<1>(); else cp_wait<0>();
        __syncthreads();

        const float* Asb = As[buf];
        const float* Bsb = Bs[buf];
        #pragma unroll
        for (int kk = 0; kk < 4; kk++) {
            uint32_t a[4][4], b[4][2];
            const int col = kk * 8 + t4;
            #pragma unroll
            for (int mt = 0; mt < 4; mt++) {
                const int r0 = wm * 64 + mt * 16 + q;
                a[mt][0] = __float_as_uint(Asb[r0 * AS_STRIDE + col]);
                a[mt][1] = __float_as_uint(Asb[(r0 + 8) * AS_STRIDE + col]);
                a[mt][2] = __float_as_uint(Asb[r0 * AS_STRIDE + col + 4]);
                a[mt][3] = __float_as_uint(Asb[(r0 + 8) * AS_STRIDE + col + 4]);
            }
            #pragma unroll
            for (int nt = 0; nt < 4; nt++) {
                const int nb = wn * 32 + nt * 8 + q;
                b[nt][0] = __float_as_uint(Bsb[col * BS_STRIDE + nb]);
                b[nt][1] = __float_as_uint(Bsb[(col + 4) * BS_STRIDE + nb]);
            }
            #pragma unroll
            for (int mt = 0; mt < 4; mt++)
                #pragma unroll
                for (int nt = 0; nt < 4; nt++)
                    mma_tf32(acc[mt][nt], a[mt], b[nt]);
        }
        __syncthreads();
    }

    // ---------------- epilogue ----------------
    #pragma unroll
    for (int mt = 0; mt < 4; mt++) {
        #pragma unroll
        for (int nt = 0; nt < 4; nt++) {
            const int hl = wn * 32 + nt * 8 + 2 * t4;
            const int h  = ncol + hl;
            #pragma unroll
            for (int half = 0; half < 2; half++) {
                const int row = m0 + wm * 64 + mt * 16 + q + half * 8;
                const float v0 = acc[mt][nt][half * 2 + 0];
                const float v1 = acc[mt][nt][half * 2 + 1];
                if (MODE == 0) {
                    float2 bb2 = *(const float2*)(bias + h);
                    float2 o = make_float2(v0 + bb2.x, v1 + bb2.y);
                    *(float2*)(g_curx + (size_t)row * 1024 + seg * 256 + h) = o;
                } else if (MODE == 1) {
                    const int b = row / 10;
                    if (seg == 0) {
                        float2 cx = *(const float2*)(g_curx + (size_t)b * 1024 + h);
                        float2 o = make_float2(sigmoidf_(v0 + cx.x), sigmoidf_(v1 + cx.y));
                        *(float2*)(g_z + (size_t)row * 256 + h) = o;
                    } else {
                        float2 cx = *(const float2*)(g_curx + (size_t)b * 1024 + 256 + h);
                        float2 pv = *(const float2*)(prev + (size_t)row * 256 + h);
                        float2 o = make_float2(sigmoidf_(v0 + cx.x) * pv.x,
                                               sigmoidf_(v1 + cx.y) * pv.y);
                        *(float2*)(g_rp + (size_t)row * 256 + h) = o;
                    }
                } else if (MODE == 2) {
                    const int b = row / 10;
                    float2 cx = *(const float2*)(g_curx + (size_t)b * 1024 + 512 + h);
                    float2 zz = *(const float2*)(g_z + (size_t)row * 256 + h);
                    float2 pv = *(const float2*)(prev + (size_t)row * 256 + h);
                    float c0 = tanhf(v0 + cx.x), c1 = tanhf(v1 + cx.y);
                    float2 o = make_float2((1.f - zz.x) * pv.x + zz.x * c0,
                                           (1.f - zz.y) * pv.y + zz.y * c1);
                    *(float2*)(out + (size_t)row * 256 + h) = o;
                } else {  // MODE 3
                    float2 bb2 = *(const float2*)(bias + h);
                    float2 o = make_float2(v0 + bb2.x, v1 + bb2.y);
                    *(float2*)(g_k + (size_t)row * 256 + h) = o;
                }
            }
        }
    }
}

// ---------------------------------------------------------------------------
// Attention + fuse + LayerNorm. One CTA handles GB=16 batch rows. (fp32, mem-bound)
// ---------------------------------------------------------------------------
__global__ __launch_bounds__(256)
void attn_fuse_kernel(const float* __restrict__ cur,
                      float* __restrict__ d_out,
                      const float* __restrict__ Wo, const float* __restrict__ bo,
                      const float* __restrict__ gamma, const float* __restrict__ beta)
{
    const int GB = 16;
    __shared__ __align__(16) float sbuf[GB * 512];
    __shared__ float ss[GB * 8 * 10];
    __shared__ float sattn[GB * 10];
    const int tid = threadIdx.x;
    const int b0 = blockIdx.x * GB;
    float* upd      = d_out + (size_t)B_ * 256;
    float* attn_out = d_out + (size_t)B_ * 256 + (size_t)BM_ * 256;

    // A: load q
    for (int idx = tid; idx < GB * 256; idx += 256) {
        int bi = idx >> 8, h = idx & 255;
        sbuf[bi * 512 + h] = g_curx[(size_t)(b0 + bi) * 1024 + 768 + h];
    }
    __syncthreads();

    // B: scores
    const float scale = 0.17677669529663687f;
    for (int t = tid; t < GB * 80; t += 256) {
        int bi = t / 80, rem = t % 80, n = rem / 10, m = rem % 10;
        const float* kp = g_k + ((size_t)((b0 + bi) * 10 + m)) * 256 + n * 32;
        const float* qp = sbuf + bi * 512 + n * 32;
        float s = 0.f;
        #pragma unroll
        for (int d4 = 0; d4 < 32; d4 += 4) {
            float4 kv = *(const float4*)(kp + d4);
            float4 qv = *(const float4*)(qp + d4);
            s += kv.x * qv.x + kv.y * qv.y + kv.z * qv.z + kv.w * qv.w;
        }
        ss[t] = s * scale;
    }
    __syncthreads();

    // C: softmax over m
    for (int t = tid; t < GB * 8; t += 256) {
        float* row = ss + t * 10;
        float mx = row[0];
        #pragma unroll
        for (int m = 1; m < 10; m++) mx = fmaxf(mx, row[m]);
        float e[10], sum = 0.f;
        #pragma unroll
        for (int m = 0; m < 10; m++) { e[m] = expf(row[m] - mx); sum += e[m]; }
        float inv = 1.f / sum;
        #pragma unroll
        for (int m = 0; m < 10; m++) row[m] = e[m] * inv;
    }
    __syncthreads();

    // head mean
    for (int t = tid; t < GB * 10; t += 256) {
        int bi = t / 10, m = t % 10;
        float s = 0.f;
        #pragma unroll
        for (int n = 0; n < 8; n++) s += ss[(bi * 8 + n) * 10 + m];
        s *= 0.125f;
        sattn[t] = s;
        attn_out[(size_t)(b0 + bi) * 10 + m] = s;
    }
    __syncthreads();

    // D: weighted memory; x = [cur | weighted]
    for (int idx = tid; idx < GB * 256; idx += 256) {
        int bi = idx >> 8, h = idx & 255;
        size_t base = ((size_t)(b0 + bi) * 10) * 256 + h;
        float s = 0.f;
        #pragma unroll
        for (int m = 0; m < 10; m++) s += upd[base + m * 256] * sattn[bi * 10 + m];
        sbuf[bi * 512 + h]       = cur[(size_t)(b0 + bi) * 256 + h];
        sbuf[bi * 512 + 256 + h] = s;
    }
    __syncthreads();

    // E: fused_pre = x @ Wo + bo
    float accv[GB];
    #pragma unroll
    for (int bi = 0; bi < GB; bi++) accv[bi] = bo[tid];
    for (int c = 0; c < 512; c += 4) {
        float w0 = Wo[(size_t)(c + 0) * 256 + tid];
        float w1 = Wo[(size_t)(c + 1) * 256 + tid];
        float w2 = Wo[(size_t)(c + 2) * 256 + tid];
        float w3 = Wo[(size_t)(c + 3) * 256 + tid];
        #pragma unroll
        for (int bi = 0; bi < GB; bi++) {
            float4 xv = *(const float4*)(sbuf + bi * 512 + c);
            accv[bi] += xv.x * w0 + xv.y * w1 + xv.z * w2 + xv.w * w3;
        }
    }
    __syncthreads();
    #pragma unroll
    for (int bi = 0; bi < GB; bi++) sbuf[bi * 256 + tid] = accv[bi];
    __syncthreads();

    // F: LayerNorm
    int wid = tid >> 5, lane = tid & 31;
    for (int bi = wid; bi < GB; bi += 8) {
        float v[8], sum = 0.f;
        #pragma unroll
        for (int i = 0; i < 8; i++) { v[i] = sbuf[bi * 256 + lane + 32 * i]; sum += v[i]; }
        #pragma unroll
        for (int o = 16; o > 0; o >>= 1) sum += __shfl_xor_sync(0xffffffffu, sum, o);
        float mu = sum * (1.f / 256.f);
        float sq = 0.f;
        #pragma unroll
        for (int i = 0; i < 8; i++) { float d = v[i] - mu; sq += d * d; }
        #pragma unroll
        for (int o = 16; o > 0; o >>= 1) sq += __shfl_xor_sync(0xffffffffu, sq, o);
        float rstd = rsqrtf(sq * (1.f / 256.f) + 1e-5f);
        size_t ob = (size_t)(b0 + bi) * 256;
        #pragma unroll
        for (int i = 0; i < 8; i++) {
            int d_ = lane + 32 * i;
            d_out[ob + d_] = (v[i] - mu) * rstd * gamma[d_] + beta[d_];
        }
    }
}

extern "C" void kernel_launch(void* const* d_in, const int* in_sizes, int n_in,
                              void* d_out, int out_size)
{
    (void)in_sizes; (void)n_in; (void)out_size;
    const float* cur    = (const float*)d_in[0];
    const float* prev   = (const float*)d_in[1];
    const float* Wz     = (const float*)d_in[2];
    const float* bz     = (const float*)d_in[3];
    const float* Wr     = (const float*)d_in[4];
    const float* br     = (const float*)d_in[5];
    const float* Wh     = (const float*)d_in[6];
    const float* bh     = (const float*)d_in[7];
    const float* Wq     = (const float*)d_in[8];
    const float* bq     = (const float*)d_in[9];
    const float* Wk     = (const float*)d_in[10];
    const float* bk     = (const float*)d_in[11];
    const float* Wo     = (const float*)d_in[12];
    const float* bo     = (const float*)d_in[13];
    const float* gamma2 = (const float*)d_in[14];
    const float* beta2  = (const float*)d_in[15];
    float* out = (float*)d_out;
    float* upd = out + (size_t)B_ * 256;

    dim3 blk(256);
    // 1) cur projections: [B,256] @ [256,1024]
    mma_gemm<0><<<dim3(8, B_ / 128), blk>>>(cur, Wz, Wr, Wh, Wq,
                                            bz, br, bh, bq, nullptr, nullptr);
    // 2) z/r gates: [BM,256] @ [256,512]
    mma_gemm<1><<<dim3(4, BM_ / 128), blk>>>(prev, Wz + 65536, Wr + 65536, nullptr, nullptr,
                                             nullptr, nullptr, nullptr, nullptr, prev, nullptr);
    // 3) cand + GRU update -> updated_memory
    mma_gemm<2><<<dim3(2, BM_ / 128), blk>>>(nullptr, Wh + 65536, nullptr, nullptr, nullptr,
                                             nullptr, nullptr, nullptr, nullptr, prev, upd);
    // 4) k projection
    mma_gemm<3><<<dim3(2, BM_ / 128), blk>>>(upd, Wk, nullptr, nullptr, nullptr,
                                             bk, nullptr, nullptr, nullptr, nullptr, nullptr);
    // 5) attention + weighted memory + output proj + layernorm
    attn_fuse_kernel<<<dim3(B_ / 16), blk>>>(cur, out, Wo, bo, gamma2, beta2);
}